// round 10
// baseline (speedup 1.0000x reference)
#include <cuda_runtime.h>
#include <cuda_bf16.h>
#include <math.h>
#include <stdint.h>

// Problem constants
#define BB   2
#define TT   1024
#define CC   2048
#define HH   16
#define DD   128
#define PP   1024
#define TOTL 2048
#define BHN  32

#define STAGE_BYTES 32768
#define NSTAGE      3
#define DSMEM       (NSTAGE * STAGE_BYTES)   // 96 KB (2 CTA/SM)

// flash kernel smem: 4-stage chunk ring (4KB hi + 4KB lo per stage) + Q
#define FL_STAGE  8192
#define FL_NST    4
#define FL_QOFF   (FL_NST * FL_STAGE)        // 32768
#define FL_DSMEM  (FL_QOFF + 32768)          // 65536  (3 CTA/SM)

// ---------------------------------------------------------------------------
// Device scratch (allocation-free)
// ---------------------------------------------------------------------------
__device__ __nv_bfloat16 g_xh [(size_t)CC * CC], g_xl [(size_t)CC * CC];
__device__ __nv_bfloat16 g_wqh[(size_t)CC * CC], g_wql[(size_t)CC * CC];
__device__ __nv_bfloat16 g_wkh[(size_t)CC * CC], g_wkl[(size_t)CC * CC];
__device__ __nv_bfloat16 g_wvh[(size_t)CC * CC], g_wvl[(size_t)CC * CC];
__device__ __nv_bfloat16 g_wph[(size_t)CC * CC], g_wpl[(size_t)CC * CC];
__device__ __nv_bfloat16 g_qh [(size_t)BHN * TT * DD],   g_ql [(size_t)BHN * TT * DD];
__device__ __nv_bfloat16 g_kh [(size_t)BHN * TOTL * DD], g_kl [(size_t)BHN * TOTL * DD];
__device__ __nv_bfloat16 g_vth[(size_t)BHN * DD * TOTL], g_vtl[(size_t)BHN * DD * TOTL];
__device__ __nv_bfloat16 g_aoh[(size_t)BB * TT * CC],    g_aol[(size_t)BB * TT * CC];

__device__ __forceinline__ uint32_t smem_u32(const void* p) {
    uint32_t a;
    asm("{ .reg .u64 t; cvta.to.shared.u64 t, %1; cvt.u32.u64 %0, t; }" : "=r"(a) : "l"(p));
    return a;
}
__device__ __forceinline__ void split2(float v, __nv_bfloat16& h, __nv_bfloat16& l) {
    h = __float2bfloat16(v);
    l = __float2bfloat16(v - __bfloat162float(h));
}
__device__ __forceinline__ uint32_t packbf(__nv_bfloat16 a, __nv_bfloat16 b) {
    __nv_bfloat162 t; t.x = a; t.y = b;
    return *(uint32_t*)&t;
}
__device__ __forceinline__ void cpasync16(uint32_t dst, const void* src) {
    asm volatile("cp.async.cg.shared.global [%0], [%1], 16;" :: "r"(dst), "l"(src));
}
#define CP_COMMIT() asm volatile("cp.async.commit_group;" ::: "memory")
#define CP_WAIT1()  asm volatile("cp.async.wait_group 1;"  ::: "memory")
#define CP_WAIT2()  asm volatile("cp.async.wait_group 2;"  ::: "memory")

#define LDM4(r, addr)                                                        \
    asm volatile("ldmatrix.sync.aligned.m8n8.x4.shared.b16 {%0,%1,%2,%3}, [%4];" \
        : "=r"((r)[0]), "=r"((r)[1]), "=r"((r)[2]), "=r"((r)[3]) : "r"(addr))

#define MMA16816(c, a, b0v, b1v)                                             \
    asm volatile("mma.sync.aligned.m16n8k16.row.col.f32.bf16.bf16.f32 "      \
        "{%0,%1,%2,%3}, {%4,%5,%6,%7}, {%8,%9}, {%0,%1,%2,%3};"              \
        : "+f"((c)[0]), "+f"((c)[1]), "+f"((c)[2]), "+f"((c)[3])             \
        : "r"((a)[0]), "r"((a)[1]), "r"((a)[2]), "r"((a)[3]),                \
          "r"(b0v), "r"(b1v))

__device__ __forceinline__ uint32_t swz(uint32_t o) { return o ^ ((o >> 3) & 0x30); }

// ---------------------------------------------------------------------------
// Dense GEMM mainloop: 3-stage cp.async ring, 8 warps 4x2, CTA 128x128,
// K-chunk 32, C = AhBh + AlBh + AhBl (term groups separated).
// ---------------------------------------------------------------------------
struct Frag { float c[2][8][4]; };

__device__ __forceinline__ void mma_mainloop(
    char* smem,
    const __nv_bfloat16* __restrict__ Ah, const __nv_bfloat16* __restrict__ Al,
    const __nv_bfloat16* __restrict__ Bh, const __nv_bfloat16* __restrict__ Bl,
    size_t ldA, size_t ldB, int NC, Frag& F)
{
    const uint32_t sb = smem_u32(smem);
    const int tid  = threadIdx.x;
    const int lane = tid & 31;
    const int wid  = tid >> 5;
    const int wm   = wid & 3;
    const int wn   = wid >> 2;

#pragma unroll
    for (int i = 0; i < 2; i++)
#pragma unroll
        for (int j = 0; j < 8; j++)
#pragma unroll
            for (int k = 0; k < 4; k++) F.c[i][j][k] = 0.f;

    const __nv_bfloat16* gp[8];
    uint32_t soff[8];
#pragma unroll
    for (int j = 0; j < 8; j++) {
        int u = tid + 256 * (j & 1);
        int row = u >> 2, un = u & 3, T = j >> 1;
        const __nv_bfloat16* base = (T == 0) ? Ah : (T == 1) ? Al : (T == 2) ? Bh : Bl;
        size_t ld = (T < 2) ? ldA : ldB;
        gp[j]   = base + (size_t)row * ld + un * 8;
        soff[j] = T * 8192 + swz(row * 64 + un * 16);
    }

    uint32_t aoff[2][2], boff[4][2];
#pragma unroll
    for (int mt = 0; mt < 2; mt++)
#pragma unroll
        for (int kk = 0; kk < 2; kk++) {
            int row = wm * 32 + mt * 16 + (lane & 15);
            aoff[mt][kk] = swz(row * 64 + kk * 32 + ((lane >> 4) & 1) * 16);
        }
#pragma unroll
    for (int bt = 0; bt < 4; bt++)
#pragma unroll
        for (int kk = 0; kk < 2; kk++) {
            int row = wn * 64 + bt * 16 + (lane & 7) + ((lane >> 4) & 1) * 8;
            boff[bt][kk] = swz(row * 64 + kk * 32 + ((lane >> 3) & 1) * 16);
        }

#pragma unroll
    for (int p = 0; p < 2; p++) {
        if (p < NC) {
            uint32_t st = sb + p * STAGE_BYTES;
#pragma unroll
            for (int j = 0; j < 8; j++)
                cpasync16(st + soff[j], gp[j] + (size_t)p * 32);
        }
        CP_COMMIT();
    }

    int stage = 0;
    for (int ch = 0; ch < NC; ch++) {
        CP_WAIT1();
        __syncthreads();

        const int pf = ch + 2;
        if (pf < NC) {
            int pstage = stage + 2; if (pstage >= NSTAGE) pstage -= NSTAGE;
            uint32_t st = sb + pstage * STAGE_BYTES;
#pragma unroll
            for (int j = 0; j < 8; j++)
                cpasync16(st + soff[j], gp[j] + (size_t)pf * 32);
        }
        CP_COMMIT();

        const uint32_t stb = sb + stage * STAGE_BYTES;
#pragma unroll
        for (int kk = 0; kk < 2; kk++) {
            uint32_t ah[2][4], al[2][4], bf4[4][4];
#pragma unroll
            for (int mt = 0; mt < 2; mt++) LDM4(ah[mt], stb + aoff[mt][kk]);
#pragma unroll
            for (int mt = 0; mt < 2; mt++) LDM4(al[mt], stb + 8192 + aoff[mt][kk]);
#pragma unroll
            for (int bt = 0; bt < 4; bt++) LDM4(bf4[bt], stb + 16384 + boff[bt][kk]);
#pragma unroll
            for (int mt = 0; mt < 2; mt++)
#pragma unroll
                for (int bt = 0; bt < 4; bt++) {
                    MMA16816(F.c[mt][bt * 2 + 0], ah[mt], bf4[bt][0], bf4[bt][1]);
                    MMA16816(F.c[mt][bt * 2 + 1], ah[mt], bf4[bt][2], bf4[bt][3]);
                }
#pragma unroll
            for (int mt = 0; mt < 2; mt++)
#pragma unroll
                for (int bt = 0; bt < 4; bt++) {
                    MMA16816(F.c[mt][bt * 2 + 0], al[mt], bf4[bt][0], bf4[bt][1]);
                    MMA16816(F.c[mt][bt * 2 + 1], al[mt], bf4[bt][2], bf4[bt][3]);
                }
#pragma unroll
            for (int bt = 0; bt < 4; bt++) LDM4(bf4[bt], stb + 24576 + boff[bt][kk]);
#pragma unroll
            for (int mt = 0; mt < 2; mt++)
#pragma unroll
                for (int bt = 0; bt < 4; bt++) {
                    MMA16816(F.c[mt][bt * 2 + 0], ah[mt], bf4[bt][0], bf4[bt][1]);
                    MMA16816(F.c[mt][bt * 2 + 1], ah[mt], bf4[bt][2], bf4[bt][3]);
                }
        }
        if (++stage == NSTAGE) stage = 0;
    }
}

// ---------------------------------------------------------------------------
// Fused prep: tasks 0-4 split {x,Wq,Wk,Wv,Wp}; 5 = past_k copy+split; 6 = past_v copy
// ---------------------------------------------------------------------------
__global__ void __launch_bounds__(256) prep_kernel(
    const float4* __restrict__ x,  const float4* __restrict__ Wq,
    const float4* __restrict__ Wk, const float4* __restrict__ Wv,
    const float4* __restrict__ Wp, const float4* __restrict__ pk,
    const float4* __restrict__ pv, float4* __restrict__ outk,
    float4* __restrict__ outv)
{
    const int task = blockIdx.y;
    const int i = blockIdx.x * blockDim.x + threadIdx.x;

    if (task == 6) {
        int bh = i >> 15, rem = i & 32767;
        outv[(size_t)bh * (TOTL * DD / 4) + rem] = pv[i];
        return;
    }

    float4 v;
    __nv_bfloat162 *dh, *dl;
    size_t o2;
    if (task == 5) {
        int bh = i >> 15, rem = i & 32767;
        size_t d4 = (size_t)bh * (TOTL * DD / 4) + rem;
        v = pk[i];
        outk[d4] = v;
        dh = (__nv_bfloat162*)g_kh; dl = (__nv_bfloat162*)g_kl;
        o2 = 2 * d4;
    } else {
        const float4* s = (task == 0) ? x : (task == 1) ? Wq :
                          (task == 2) ? Wk : (task == 3) ? Wv : Wp;
        v = s[i];
        dh = (__nv_bfloat162*)((task == 0) ? g_xh : (task == 1) ? g_wqh :
                               (task == 2) ? g_wkh : (task == 3) ? g_wvh : g_wph);
        dl = (__nv_bfloat162*)((task == 0) ? g_xl : (task == 1) ? g_wql :
                               (task == 2) ? g_wkl : (task == 3) ? g_wvl : g_wpl);
        o2 = 2 * (size_t)i;
    }
    __nv_bfloat16 h0, h1, h2, h3, l0, l1, l2, l3;
    split2(v.x, h0, l0); split2(v.y, h1, l1);
    split2(v.z, h2, l2); split2(v.w, h3, l3);
    __nv_bfloat162 H0; H0.x = h0; H0.y = h1;
    __nv_bfloat162 H1; H1.x = h2; H1.y = h3;
    __nv_bfloat162 L0; L0.x = l0; L0.y = l1;
    __nv_bfloat162 L1; L1.x = l2; L1.y = l3;
    dh[o2] = H0; dh[o2 + 1] = H1;
    dl[o2] = L0; dl[o2 + 1] = L1;
}

// v[bh][j][d] fp32 -> vt hi/lo [bh][d][j] bf16
__global__ void __launch_bounds__(256) vtrans_kernel(const float* __restrict__ v)
{
    __shared__ float tile[32][33];
    const int bh = blockIdx.z;
    const int j0 = blockIdx.x * 32, d0 = blockIdx.y * 32;
    const int tx = threadIdx.x & 31, ty = threadIdx.x >> 5;
    const float* src = v + (size_t)bh * TOTL * DD;
#pragma unroll
    for (int i = 0; i < 4; i++)
        tile[ty + i * 8][tx] = src[(size_t)(j0 + ty + i * 8) * DD + d0 + tx];
    __syncthreads();
    __nv_bfloat16* dh = g_vth + (size_t)bh * DD * TOTL;
    __nv_bfloat16* dl = g_vtl + (size_t)bh * DD * TOTL;
#pragma unroll
    for (int i = 0; i < 4; i++) {
        int d = d0 + ty + i * 8, j = j0 + tx;
        float val = tile[tx][ty + i * 8];
        __nv_bfloat16 h, l; split2(val, h, l);
        dh[(size_t)d * TOTL + j] = h;
        dl[(size_t)d * TOTL + j] = l;
    }
}

// ---------------------------------------------------------------------------
// QKV projection: y = x @ W^T, z selects {Wq, Wk, Wv}
// ---------------------------------------------------------------------------
__global__ void __launch_bounds__(256, 2) qkv_mma(float* __restrict__ outk,
                                                  float* __restrict__ outv)
{
    extern __shared__ __align__(1024) char smem[];
    const int z = blockIdx.z;
    const int m0 = blockIdx.y * 128, n0 = blockIdx.x * 128;
    const __nv_bfloat16* Bh = (z == 0) ? g_wqh : (z == 1) ? g_wkh : g_wvh;
    const __nv_bfloat16* Bl = (z == 0) ? g_wql : (z == 1) ? g_wkl : g_wvl;
    Frag F;
    mma_mainloop(smem,
        g_xh + (size_t)m0 * CC, g_xl + (size_t)m0 * CC,
        Bh + (size_t)n0 * CC,   Bl + (size_t)n0 * CC, CC, CC, 64, F);

    const int lane = threadIdx.x & 31, wid = threadIdx.x >> 5;
    const int wm = wid & 3, wn = wid >> 2;
#pragma unroll
    for (int mt = 0; mt < 2; mt++)
#pragma unroll
        for (int half = 0; half < 2; half++) {
            int m = m0 + wm * 32 + mt * 16 + lane / 4 + half * 8;
            int b = m >> 10, t = m & 1023;
#pragma unroll
            for (int nt = 0; nt < 8; nt++) {
                int n = n0 + wn * 64 + nt * 8 + (lane & 3) * 2;
                int h = n >> 7, d = n & 127;
                float v0 = F.c[mt][nt][half * 2], v1 = F.c[mt][nt][half * 2 + 1];
                __nv_bfloat16 h0, h1, l0, l1;
                if (z == 0) {
                    size_t base = (((size_t)(b * 16 + h)) * 1024 + t) * 128 + d;
                    split2(v0, h0, l0); split2(v1, h1, l1);
                    *(uint32_t*)(g_qh + base) = packbf(h0, h1);
                    *(uint32_t*)(g_ql + base) = packbf(l0, l1);
                } else if (z == 1) {
                    size_t base = (((size_t)(b * 16 + h)) * 2048 + 1024 + t) * 128 + d;
                    *(float2*)(outk + base) = make_float2(v0, v1);
                    split2(v0, h0, l0); split2(v1, h1, l1);
                    *(uint32_t*)(g_kh + base) = packbf(h0, h1);
                    *(uint32_t*)(g_kl + base) = packbf(l0, l1);
                } else {
                    size_t base = (((size_t)(b * 16 + h)) * 2048 + 1024 + t) * 128 + d;
                    *(float2*)(outv + base) = make_float2(v0, v1);
                }
            }
        }
}

// ---------------------------------------------------------------------------
// Flash attention: 64 q-rows per CTA, 128 threads, 64-wide j-tiles,
// 3 CTAs/SM. Chunk = 64 rows x 32 cols (4KB hi + 4KB lo).
// Stream per j-tile: K(d-chunk 0..3), V(j0,d0),(j0,d1),(j1,d0),(j1,d1).
// ---------------------------------------------------------------------------
__device__ __forceinline__ void fl_issue(uint32_t sb, int bh, int idx, int stg, int tid)
{
    const int jt = idx >> 3, sub = idx & 7;
    const int j0 = jt * 64;
    const __nv_bfloat16 *sh, *sl;
    size_t ld;
    if (sub < 4) {
        size_t base = ((size_t)bh * TOTL + j0) * DD + sub * 32;
        sh = g_kh + base; sl = g_kl + base;
        ld = DD;
    } else {
        int jb = (sub - 4) >> 1, db = (sub - 4) & 1;
        size_t base = (size_t)bh * DD * TOTL + (size_t)(db * 64) * TOTL + j0 + jb * 32;
        sh = g_vth + base; sl = g_vtl + base;
        ld = TOTL;
    }
    uint32_t st = sb + stg * FL_STAGE;
#pragma unroll
    for (int j = 0; j < 2; j++) {
        int u = tid + 128 * j, row = u >> 2, un = u & 3;
        uint32_t so = swz(row * 64 + un * 16);
        cpasync16(st + so,        sh + (size_t)row * ld + un * 8);
        cpasync16(st + 4096 + so, sl + (size_t)row * ld + un * 8);
    }
}

__global__ void __launch_bounds__(128, 3) flash_mma()
{
    extern __shared__ __align__(1024) char smem[];
    const uint32_t sb = smem_u32(smem);
    const int bh = blockIdx.z;
    const int m0 = (15 - blockIdx.y) * 64;    // long CTAs first
    const int b = bh >> 4, h = bh & 15;
    const int tid = threadIdx.x;
    const int lane = tid & 31;
    const int w = tid >> 5;
    const int r0 = lane >> 2;
    const int NJ = (1088 + m0) >> 6;          // 17..32 j-tiles of 64
    const int NCH = NJ * 8;

    // Q tile: 64 rows, 4 d-chunks x (hi,lo); hi at FL_QOFF, lo at +16384
#pragma unroll
    for (int c = 0; c < 4; c++)
#pragma unroll
        for (int j = 0; j < 2; j++) {
            int u = tid + 128 * j, row = u >> 2, un = u & 3;
            uint32_t so = c * 4096 + swz(row * 64 + un * 16);
            cpasync16(sb + FL_QOFF + so,
                      g_qh + ((size_t)bh * TT + m0 + row) * DD + c * 32 + un * 8);
            cpasync16(sb + FL_QOFF + 16384 + so,
                      g_ql + ((size_t)bh * TT + m0 + row) * DD + c * 32 + un * 8);
        }
    CP_COMMIT();
    fl_issue(sb, bh, 0, 0, tid); CP_COMMIT();
    fl_issue(sb, bh, 1, 1, tid); CP_COMMIT();
    fl_issue(sb, bh, 2, 2, tid); CP_COMMIT();

    uint32_t aoff[2], boff[4][2];
#pragma unroll
    for (int kk = 0; kk < 2; kk++) {
        int row = w * 16 + (lane & 15);
        aoff[kk] = swz(row * 64 + kk * 32 + ((lane >> 4) & 1) * 16);
    }
#pragma unroll
    for (int bt = 0; bt < 4; bt++)
#pragma unroll
        for (int kk = 0; kk < 2; kk++) {
            int row = bt * 16 + (lane & 7) + ((lane >> 4) & 1) * 8;
            boff[bt][kk] = swz(row * 64 + kk * 32 + ((lane >> 3) & 1) * 16);
        }

    float O[16][4];
#pragma unroll
    for (int i = 0; i < 16; i++)
#pragma unroll
        for (int k = 0; k < 4; k++) O[i][k] = 0.f;
    float ml0 = -1e30f, ml1 = -1e30f;
    float ll0 = 0.f, ll1 = 0.f;
    uint32_t ph[4][4], pl[4][4];

    int pf = 3, stage = 0;
    const float scale = 0.08838834764831845f;

    for (int jt = 0; jt < NJ; jt++) {
        float Sf[8][4];
        // ---- S phase: 4 K d-chunks ----
#pragma unroll
        for (int ch = 0; ch < 4; ch++) {
            CP_WAIT2();
            __syncthreads();
            int pst = stage + 3; if (pst >= FL_NST) pst -= FL_NST;
            if (pf < NCH) fl_issue(sb, bh, pf, pst, tid);
            CP_COMMIT();
            pf++;
            const uint32_t stb = sb + stage * FL_STAGE;
            const uint32_t qb  = sb + FL_QOFF + ch * 4096;
            if (ch == 0) {
#pragma unroll
                for (int i = 0; i < 8; i++)
#pragma unroll
                    for (int k = 0; k < 4; k++) Sf[i][k] = 0.f;
            }
#pragma unroll
            for (int kk = 0; kk < 2; kk++) {
                uint32_t ahf[4], alf[4], bf[4][4];
                LDM4(ahf, qb + aoff[kk]);
                LDM4(alf, qb + 16384 + aoff[kk]);
#pragma unroll
                for (int bt = 0; bt < 4; bt++) LDM4(bf[bt], stb + boff[bt][kk]);
#pragma unroll
                for (int bt = 0; bt < 4; bt++) {
                    MMA16816(Sf[bt * 2 + 0], ahf, bf[bt][0], bf[bt][1]);
                    MMA16816(Sf[bt * 2 + 1], ahf, bf[bt][2], bf[bt][3]);
                }
#pragma unroll
                for (int bt = 0; bt < 4; bt++) {
                    MMA16816(Sf[bt * 2 + 0], alf, bf[bt][0], bf[bt][1]);
                    MMA16816(Sf[bt * 2 + 1], alf, bf[bt][2], bf[bt][3]);
                }
#pragma unroll
                for (int bt = 0; bt < 4; bt++) LDM4(bf[bt], stb + 4096 + boff[bt][kk]);
#pragma unroll
                for (int bt = 0; bt < 4; bt++) {
                    MMA16816(Sf[bt * 2 + 0], ahf, bf[bt][0], bf[bt][1]);
                    MMA16816(Sf[bt * 2 + 1], ahf, bf[bt][2], bf[bt][3]);
                }
            }
            if (++stage == FL_NST) stage = 0;
        }

        // ---- online softmax on 64-wide tile ----
#pragma unroll
        for (int nt = 0; nt < 8; nt++)
#pragma unroll
            for (int ci = 0; ci < 4; ci++) Sf[nt][ci] *= scale;
        if (jt == NJ - 1) {
            // exactly triangular: local col jj valid iff jj <= local row
#pragma unroll
            for (int nt = 0; nt < 8; nt++)
#pragma unroll
                for (int ci = 0; ci < 4; ci++) {
                    int jj = nt * 8 + (lane & 3) * 2 + (ci & 1);
                    int tl = w * 16 + r0 + ((ci >> 1) << 3);
                    if (jj > tl) Sf[nt][ci] = -1e30f;
                }
        }
        float mc0 = -1e30f, mc1 = -1e30f;
#pragma unroll
        for (int nt = 0; nt < 8; nt++) {
            mc0 = fmaxf(mc0, fmaxf(Sf[nt][0], Sf[nt][1]));
            mc1 = fmaxf(mc1, fmaxf(Sf[nt][2], Sf[nt][3]));
        }
        mc0 = fmaxf(mc0, __shfl_xor_sync(0xffffffffu, mc0, 1));
        mc0 = fmaxf(mc0, __shfl_xor_sync(0xffffffffu, mc0, 2));
        mc1 = fmaxf(mc1, __shfl_xor_sync(0xffffffffu, mc1, 1));
        mc1 = fmaxf(mc1, __shfl_xor_sync(0xffffffffu, mc1, 2));
        float mn0 = fmaxf(ml0, mc0), mn1 = fmaxf(ml1, mc1);
        float a0 = __expf(ml0 - mn0), a1 = __expf(ml1 - mn1);
        ml0 = mn0; ml1 = mn1;
        ll0 *= a0; ll1 *= a1;
#pragma unroll
        for (int nt = 0; nt < 16; nt++) {
            O[nt][0] *= a0; O[nt][1] *= a0;
            O[nt][2] *= a1; O[nt][3] *= a1;
        }
#pragma unroll
        for (int nt = 0; nt < 8; nt++) {
            float p0 = __expf(Sf[nt][0] - mn0), p1 = __expf(Sf[nt][1] - mn0);
            float p2 = __expf(Sf[nt][2] - mn1), p3 = __expf(Sf[nt][3] - mn1);
            ll0 += p0 + p1; ll1 += p2 + p3;
            __nv_bfloat16 h0, h1, h2, h3, l0, l1, l2, l3;
            split2(p0, h0, l0); split2(p1, h1, l1);
            split2(p2, h2, l2); split2(p3, h3, l3);
            int kkj = nt >> 1, half = nt & 1;
            ph[kkj][half * 2 + 0] = packbf(h0, h1);
            ph[kkj][half * 2 + 1] = packbf(h2, h3);
            pl[kkj][half * 2 + 0] = packbf(l0, l1);
            pl[kkj][half * 2 + 1] = packbf(l2, l3);
        }

        // ---- PV phase: 4 V chunks (jb outer, db inner) ----
#pragma unroll
        for (int vc = 0; vc < 4; vc++) {
            CP_WAIT2();
            __syncthreads();
            int pst = stage + 3; if (pst >= FL_NST) pst -= FL_NST;
            if (pf < NCH) fl_issue(sb, bh, pf, pst, tid);
            CP_COMMIT();
            pf++;
            const uint32_t stb = sb + stage * FL_STAGE;
            const int jb = vc >> 1, db = vc & 1;
#pragma unroll
            for (int kk = 0; kk < 2; kk++) {
                const int kkj = jb * 2 + kk;
                uint32_t vf[4][4];
#pragma unroll
                for (int dt = 0; dt < 4; dt++) LDM4(vf[dt], stb + boff[dt][kk]);
#pragma unroll
                for (int dt = 0; dt < 4; dt++) {
                    MMA16816(O[db * 8 + dt * 2 + 0], ph[kkj], vf[dt][0], vf[dt][1]);
                    MMA16816(O[db * 8 + dt * 2 + 1], ph[kkj], vf[dt][2], vf[dt][3]);
                }
#pragma unroll
                for (int dt = 0; dt < 4; dt++) {
                    MMA16816(O[db * 8 + dt * 2 + 0], pl[kkj], vf[dt][0], vf[dt][1]);
                    MMA16816(O[db * 8 + dt * 2 + 1], pl[kkj], vf[dt][2], vf[dt][3]);
                }
#pragma unroll
                for (int dt = 0; dt < 4; dt++) LDM4(vf[dt], stb + 4096 + boff[dt][kk]);
#pragma unroll
                for (int dt = 0; dt < 4; dt++) {
                    MMA16816(O[db * 8 + dt * 2 + 0], ph[kkj], vf[dt][0], vf[dt][1]);
                    MMA16816(O[db * 8 + dt * 2 + 1], ph[kkj], vf[dt][2], vf[dt][3]);
                }
            }
            if (++stage == FL_NST) stage = 0;
        }
    }

    // ---- epilogue ----
    ll0 += __shfl_xor_sync(0xffffffffu, ll0, 1);
    ll0 += __shfl_xor_sync(0xffffffffu, ll0, 2);
    ll1 += __shfl_xor_sync(0xffffffffu, ll1, 1);
    ll1 += __shfl_xor_sync(0xffffffffu, ll1, 2);
    const float inv0 = 1.f / ll0, inv1 = 1.f / ll1;
    const int t0 = m0 + w * 16 + r0, t1 = t0 + 8;
#pragma unroll
    for (int nt = 0; nt < 16; nt++) {
        int d = nt * 8 + (lane & 3) * 2;
        float v0 = O[nt][0] * inv0, v1 = O[nt][1] * inv0;
        float v2 = O[nt][2] * inv1, v3 = O[nt][3] * inv1;
        size_t b0 = ((size_t)(b * 1024 + t0)) * 2048 + h * 128 + d;
        size_t b1 = ((size_t)(b * 1024 + t1)) * 2048 + h * 128 + d;
        __nv_bfloat16 h0, h1, h2, h3, l0, l1, l2, l3;
        split2(v0, h0, l0); split2(v1, h1, l1);
        split2(v2, h2, l2); split2(v3, h3, l3);
        *(uint32_t*)(g_aoh + b0) = packbf(h0, h1);
        *(uint32_t*)(g_aol + b0) = packbf(l0, l1);
        *(uint32_t*)(g_aoh + b1) = packbf(h2, h3);
        *(uint32_t*)(g_aol + b1) = packbf(l2, l3);
    }
}

// ---------------------------------------------------------------------------
// Output projection: out = ao @ Wp^T + bp
// ---------------------------------------------------------------------------
__global__ void __launch_bounds__(256, 2) proj_mma(const float* __restrict__ bp,
                                                    float* __restrict__ out)
{
    extern __shared__ __align__(1024) char smem[];
    const int m0 = blockIdx.y * 128, n0 = blockIdx.x * 128;
    Frag F;
    mma_mainloop(smem,
        g_aoh + (size_t)m0 * CC, g_aol + (size_t)m0 * CC,
        g_wph + (size_t)n0 * CC, g_wpl + (size_t)n0 * CC, CC, CC, 64, F);

    const int lane = threadIdx.x & 31, wid = threadIdx.x >> 5;
    const int wm = wid & 3, wn = wid >> 2;
#pragma unroll
    for (int mt = 0; mt < 2; mt++)
#pragma unroll
        for (int half = 0; half < 2; half++) {
            int m = m0 + wm * 32 + mt * 16 + lane / 4 + half * 8;
#pragma unroll
            for (int nt = 0; nt < 8; nt++) {
                int n = n0 + wn * 64 + nt * 8 + (lane & 3) * 2;
                float2 bias = *(const float2*)(bp + n);
                *(float2*)(out + (size_t)m * 2048 + n) =
                    make_float2(F.c[mt][nt][half * 2] + bias.x,
                                F.c[mt][nt][half * 2 + 1] + bias.y);
            }
        }
}

// ---------------------------------------------------------------------------
extern "C" void kernel_launch(void* const* d_in, const int* in_sizes, int n_in,
                              void* d_out, int out_size)
{
    (void)in_sizes; (void)n_in; (void)out_size;
    const float* x      = (const float*)d_in[0];
    const float* past_k = (const float*)d_in[1];
    const float* past_v = (const float*)d_in[2];
    const float* Wk     = (const float*)d_in[3];
    const float* Wq     = (const float*)d_in[4];
    const float* Wv     = (const float*)d_in[5];
    const float* Wp     = (const float*)d_in[6];
    const float* bp     = (const float*)d_in[7];

    float* out  = (float*)d_out;
    float* outk = out + (size_t)BB * TT * CC;
    float* outv = outk + (size_t)BHN * TOTL * DD;

    cudaFuncSetAttribute(qkv_mma,   cudaFuncAttributeMaxDynamicSharedMemorySize, DSMEM);
    cudaFuncSetAttribute(proj_mma,  cudaFuncAttributeMaxDynamicSharedMemorySize, DSMEM);
    cudaFuncSetAttribute(flash_mma, cudaFuncAttributeMaxDynamicSharedMemorySize, FL_DSMEM);

    // 1-2. fused prep
    prep_kernel<<<dim3(4096, 7), 256>>>(
        (const float4*)x,  (const float4*)Wq, (const float4*)Wk,
        (const float4*)Wv, (const float4*)Wp, (const float4*)past_k,
        (const float4*)past_v, (float4*)outk, (float4*)outv);

    // 3. QKV projection
    qkv_mma<<<dim3(16, 16, 3), 256, DSMEM>>>(outk, outv);

    // 4. transpose+split V cache
    vtrans_kernel<<<dim3(64, 4, 32), 256>>>(outv);

    // 5-7. fused flash attention (64 q-rows per CTA, 3 CTAs/SM)
    flash_mma<<<dim3(1, 16, 32), 128, FL_DSMEM>>>();

    // 8. output projection + bias
    proj_mma<<<dim3(16, 16), 256, DSMEM>>>(bp, out);
}

// round 11
// speedup vs baseline: 1.5258x; 1.5258x over previous
#include <cuda_runtime.h>
#include <cuda_bf16.h>
#include <math.h>
#include <stdint.h>

// Problem constants
#define BB   2
#define TT   1024
#define CC   2048
#define HH   16
#define DD   128
#define PP   1024
#define TOTL 2048
#define BHN  32

#define STAGE_BYTES 32768
#define NSTAGE      3
#define DSMEM       (NSTAGE * STAGE_BYTES)   // 96 KB (2 CTA/SM)

// flash kernel smem: 4-stage K/V ring (64KB) + Q 64x128 hi/lo (32KB)
#define FL_STAGE  16384
#define FL_NST    4
#define FL_QOFF   (FL_NST * FL_STAGE)        // 65536
#define FL_DSMEM  (FL_QOFF + 32768)          // 98304 (2 CTA/SM)

// ---------------------------------------------------------------------------
// Device scratch (allocation-free)
// ---------------------------------------------------------------------------
__device__ __nv_bfloat16 g_xh [(size_t)CC * CC], g_xl [(size_t)CC * CC];
__device__ __nv_bfloat16 g_wqh[(size_t)CC * CC], g_wql[(size_t)CC * CC];
__device__ __nv_bfloat16 g_wkh[(size_t)CC * CC], g_wkl[(size_t)CC * CC];
__device__ __nv_bfloat16 g_wvh[(size_t)CC * CC], g_wvl[(size_t)CC * CC];
__device__ __nv_bfloat16 g_wph[(size_t)CC * CC], g_wpl[(size_t)CC * CC];
__device__ __nv_bfloat16 g_qh [(size_t)BHN * TT * DD],   g_ql [(size_t)BHN * TT * DD];
__device__ __nv_bfloat16 g_kh [(size_t)BHN * TOTL * DD], g_kl [(size_t)BHN * TOTL * DD];
__device__ __nv_bfloat16 g_vth[(size_t)BHN * DD * TOTL], g_vtl[(size_t)BHN * DD * TOTL];
__device__ __nv_bfloat16 g_aoh[(size_t)BB * TT * CC],    g_aol[(size_t)BB * TT * CC];

__device__ __forceinline__ uint32_t smem_u32(const void* p) {
    uint32_t a;
    asm("{ .reg .u64 t; cvta.to.shared.u64 t, %1; cvt.u32.u64 %0, t; }" : "=r"(a) : "l"(p));
    return a;
}
__device__ __forceinline__ void split2(float v, __nv_bfloat16& h, __nv_bfloat16& l) {
    h = __float2bfloat16(v);
    l = __float2bfloat16(v - __bfloat162float(h));
}
__device__ __forceinline__ uint32_t packbf(__nv_bfloat16 a, __nv_bfloat16 b) {
    __nv_bfloat162 t; t.x = a; t.y = b;
    return *(uint32_t*)&t;
}
__device__ __forceinline__ void cpasync16(uint32_t dst, const void* src) {
    asm volatile("cp.async.cg.shared.global [%0], [%1], 16;" :: "r"(dst), "l"(src));
}
#define CP_COMMIT() asm volatile("cp.async.commit_group;" ::: "memory")
#define CP_WAIT1()  asm volatile("cp.async.wait_group 1;"  ::: "memory")
#define CP_WAIT2()  asm volatile("cp.async.wait_group 2;"  ::: "memory")

#define LDM4(r, addr)                                                        \
    asm volatile("ldmatrix.sync.aligned.m8n8.x4.shared.b16 {%0,%1,%2,%3}, [%4];" \
        : "=r"((r)[0]), "=r"((r)[1]), "=r"((r)[2]), "=r"((r)[3]) : "r"(addr))

#define MMA16816(c, a, b0v, b1v)                                             \
    asm volatile("mma.sync.aligned.m16n8k16.row.col.f32.bf16.bf16.f32 "      \
        "{%0,%1,%2,%3}, {%4,%5,%6,%7}, {%8,%9}, {%0,%1,%2,%3};"              \
        : "+f"((c)[0]), "+f"((c)[1]), "+f"((c)[2]), "+f"((c)[3])             \
        : "r"((a)[0]), "r"((a)[1]), "r"((a)[2]), "r"((a)[3]),                \
          "r"(b0v), "r"(b1v))

__device__ __forceinline__ uint32_t swz(uint32_t o) { return o ^ ((o >> 3) & 0x30); }

// ---------------------------------------------------------------------------
// Dense GEMM mainloop: 3-stage cp.async ring, 8 warps 4x2, CTA 128x128,
// K-chunk 32, C = AhBh + AlBh + AhBl (term groups separated).
// ---------------------------------------------------------------------------
struct Frag { float c[2][8][4]; };

__device__ __forceinline__ void mma_mainloop(
    char* smem,
    const __nv_bfloat16* __restrict__ Ah, const __nv_bfloat16* __restrict__ Al,
    const __nv_bfloat16* __restrict__ Bh, const __nv_bfloat16* __restrict__ Bl,
    size_t ldA, size_t ldB, int NC, Frag& F)
{
    const uint32_t sb = smem_u32(smem);
    const int tid  = threadIdx.x;
    const int lane = tid & 31;
    const int wid  = tid >> 5;
    const int wm   = wid & 3;
    const int wn   = wid >> 2;

#pragma unroll
    for (int i = 0; i < 2; i++)
#pragma unroll
        for (int j = 0; j < 8; j++)
#pragma unroll
            for (int k = 0; k < 4; k++) F.c[i][j][k] = 0.f;

    const __nv_bfloat16* gp[8];
    uint32_t soff[8];
#pragma unroll
    for (int j = 0; j < 8; j++) {
        int u = tid + 256 * (j & 1);
        int row = u >> 2, un = u & 3, T = j >> 1;
        const __nv_bfloat16* base = (T == 0) ? Ah : (T == 1) ? Al : (T == 2) ? Bh : Bl;
        size_t ld = (T < 2) ? ldA : ldB;
        gp[j]   = base + (size_t)row * ld + un * 8;
        soff[j] = T * 8192 + swz(row * 64 + un * 16);
    }

    uint32_t aoff[2][2], boff[4][2];
#pragma unroll
    for (int mt = 0; mt < 2; mt++)
#pragma unroll
        for (int kk = 0; kk < 2; kk++) {
            int row = wm * 32 + mt * 16 + (lane & 15);
            aoff[mt][kk] = swz(row * 64 + kk * 32 + ((lane >> 4) & 1) * 16);
        }
#pragma unroll
    for (int bt = 0; bt < 4; bt++)
#pragma unroll
        for (int kk = 0; kk < 2; kk++) {
            int row = wn * 64 + bt * 16 + (lane & 7) + ((lane >> 4) & 1) * 8;
            boff[bt][kk] = swz(row * 64 + kk * 32 + ((lane >> 3) & 1) * 16);
        }

#pragma unroll
    for (int p = 0; p < 2; p++) {
        if (p < NC) {
            uint32_t st = sb + p * STAGE_BYTES;
#pragma unroll
            for (int j = 0; j < 8; j++)
                cpasync16(st + soff[j], gp[j] + (size_t)p * 32);
        }
        CP_COMMIT();
    }

    int stage = 0;
    for (int ch = 0; ch < NC; ch++) {
        CP_WAIT1();
        __syncthreads();

        const int pf = ch + 2;
        if (pf < NC) {
            int pstage = stage + 2; if (pstage >= NSTAGE) pstage -= NSTAGE;
            uint32_t st = sb + pstage * STAGE_BYTES;
#pragma unroll
            for (int j = 0; j < 8; j++)
                cpasync16(st + soff[j], gp[j] + (size_t)pf * 32);
        }
        CP_COMMIT();

        const uint32_t stb = sb + stage * STAGE_BYTES;
#pragma unroll
        for (int kk = 0; kk < 2; kk++) {
            uint32_t ah[2][4], al[2][4], bf4[4][4];
#pragma unroll
            for (int mt = 0; mt < 2; mt++) LDM4(ah[mt], stb + aoff[mt][kk]);
#pragma unroll
            for (int mt = 0; mt < 2; mt++) LDM4(al[mt], stb + 8192 + aoff[mt][kk]);
#pragma unroll
            for (int bt = 0; bt < 4; bt++) LDM4(bf4[bt], stb + 16384 + boff[bt][kk]);
#pragma unroll
            for (int mt = 0; mt < 2; mt++)
#pragma unroll
                for (int bt = 0; bt < 4; bt++) {
                    MMA16816(F.c[mt][bt * 2 + 0], ah[mt], bf4[bt][0], bf4[bt][1]);
                    MMA16816(F.c[mt][bt * 2 + 1], ah[mt], bf4[bt][2], bf4[bt][3]);
                }
#pragma unroll
            for (int mt = 0; mt < 2; mt++)
#pragma unroll
                for (int bt = 0; bt < 4; bt++) {
                    MMA16816(F.c[mt][bt * 2 + 0], al[mt], bf4[bt][0], bf4[bt][1]);
                    MMA16816(F.c[mt][bt * 2 + 1], al[mt], bf4[bt][2], bf4[bt][3]);
                }
#pragma unroll
            for (int bt = 0; bt < 4; bt++) LDM4(bf4[bt], stb + 24576 + boff[bt][kk]);
#pragma unroll
            for (int mt = 0; mt < 2; mt++)
#pragma unroll
                for (int bt = 0; bt < 4; bt++) {
                    MMA16816(F.c[mt][bt * 2 + 0], ah[mt], bf4[bt][0], bf4[bt][1]);
                    MMA16816(F.c[mt][bt * 2 + 1], ah[mt], bf4[bt][2], bf4[bt][3]);
                }
        }
        if (++stage == NSTAGE) stage = 0;
    }
}

// ---------------------------------------------------------------------------
// Fused prep: tasks 0-4 split {x,Wq,Wk,Wv,Wp}; 5 = past_k copy+split; 6 = past_v copy
// ---------------------------------------------------------------------------
__global__ void __launch_bounds__(256) prep_kernel(
    const float4* __restrict__ x,  const float4* __restrict__ Wq,
    const float4* __restrict__ Wk, const float4* __restrict__ Wv,
    const float4* __restrict__ Wp, const float4* __restrict__ pk,
    const float4* __restrict__ pv, float4* __restrict__ outk,
    float4* __restrict__ outv)
{
    const int task = blockIdx.y;
    const int i = blockIdx.x * blockDim.x + threadIdx.x;

    if (task == 6) {
        int bh = i >> 15, rem = i & 32767;
        outv[(size_t)bh * (TOTL * DD / 4) + rem] = pv[i];
        return;
    }

    float4 v;
    __nv_bfloat162 *dh, *dl;
    size_t o2;
    if (task == 5) {
        int bh = i >> 15, rem = i & 32767;
        size_t d4 = (size_t)bh * (TOTL * DD / 4) + rem;
        v = pk[i];
        outk[d4] = v;
        dh = (__nv_bfloat162*)g_kh; dl = (__nv_bfloat162*)g_kl;
        o2 = 2 * d4;
    } else {
        const float4* s = (task == 0) ? x : (task == 1) ? Wq :
                          (task == 2) ? Wk : (task == 3) ? Wv : Wp;
        v = s[i];
        dh = (__nv_bfloat162*)((task == 0) ? g_xh : (task == 1) ? g_wqh :
                               (task == 2) ? g_wkh : (task == 3) ? g_wvh : g_wph);
        dl = (__nv_bfloat162*)((task == 0) ? g_xl : (task == 1) ? g_wql :
                               (task == 2) ? g_wkl : (task == 3) ? g_wvl : g_wpl);
        o2 = 2 * (size_t)i;
    }
    __nv_bfloat16 h0, h1, h2, h3, l0, l1, l2, l3;
    split2(v.x, h0, l0); split2(v.y, h1, l1);
    split2(v.z, h2, l2); split2(v.w, h3, l3);
    __nv_bfloat162 H0; H0.x = h0; H0.y = h1;
    __nv_bfloat162 H1; H1.x = h2; H1.y = h3;
    __nv_bfloat162 L0; L0.x = l0; L0.y = l1;
    __nv_bfloat162 L1; L1.x = l2; L1.y = l3;
    dh[o2] = H0; dh[o2 + 1] = H1;
    dl[o2] = L0; dl[o2 + 1] = L1;
}

// v[bh][j][d] fp32 -> vt hi/lo [bh][d][j] bf16
__global__ void __launch_bounds__(256) vtrans_kernel(const float* __restrict__ v)
{
    __shared__ float tile[32][33];
    const int bh = blockIdx.z;
    const int j0 = blockIdx.x * 32, d0 = blockIdx.y * 32;
    const int tx = threadIdx.x & 31, ty = threadIdx.x >> 5;
    const float* src = v + (size_t)bh * TOTL * DD;
#pragma unroll
    for (int i = 0; i < 4; i++)
        tile[ty + i * 8][tx] = src[(size_t)(j0 + ty + i * 8) * DD + d0 + tx];
    __syncthreads();
    __nv_bfloat16* dh = g_vth + (size_t)bh * DD * TOTL;
    __nv_bfloat16* dl = g_vtl + (size_t)bh * DD * TOTL;
#pragma unroll
    for (int i = 0; i < 4; i++) {
        int d = d0 + ty + i * 8, j = j0 + tx;
        float val = tile[tx][ty + i * 8];
        __nv_bfloat16 h, l; split2(val, h, l);
        dh[(size_t)d * TOTL + j] = h;
        dl[(size_t)d * TOTL + j] = l;
    }
}

// ---------------------------------------------------------------------------
// QKV projection: y = x @ W^T, z selects {Wq, Wk, Wv}
// ---------------------------------------------------------------------------
__global__ void __launch_bounds__(256, 2) qkv_mma(float* __restrict__ outk,
                                                  float* __restrict__ outv)
{
    extern __shared__ __align__(1024) char smem[];
    const int z = blockIdx.z;
    const int m0 = blockIdx.y * 128, n0 = blockIdx.x * 128;
    const __nv_bfloat16* Bh = (z == 0) ? g_wqh : (z == 1) ? g_wkh : g_wvh;
    const __nv_bfloat16* Bl = (z == 0) ? g_wql : (z == 1) ? g_wkl : g_wvl;
    Frag F;
    mma_mainloop(smem,
        g_xh + (size_t)m0 * CC, g_xl + (size_t)m0 * CC,
        Bh + (size_t)n0 * CC,   Bl + (size_t)n0 * CC, CC, CC, 64, F);

    const int lane = threadIdx.x & 31, wid = threadIdx.x >> 5;
    const int wm = wid & 3, wn = wid >> 2;
#pragma unroll
    for (int mt = 0; mt < 2; mt++)
#pragma unroll
        for (int half = 0; half < 2; half++) {
            int m = m0 + wm * 32 + mt * 16 + lane / 4 + half * 8;
            int b = m >> 10, t = m & 1023;
#pragma unroll
            for (int nt = 0; nt < 8; nt++) {
                int n = n0 + wn * 64 + nt * 8 + (lane & 3) * 2;
                int h = n >> 7, d = n & 127;
                float v0 = F.c[mt][nt][half * 2], v1 = F.c[mt][nt][half * 2 + 1];
                __nv_bfloat16 h0, h1, l0, l1;
                if (z == 0) {
                    size_t base = (((size_t)(b * 16 + h)) * 1024 + t) * 128 + d;
                    split2(v0, h0, l0); split2(v1, h1, l1);
                    *(uint32_t*)(g_qh + base) = packbf(h0, h1);
                    *(uint32_t*)(g_ql + base) = packbf(l0, l1);
                } else if (z == 1) {
                    size_t base = (((size_t)(b * 16 + h)) * 2048 + 1024 + t) * 128 + d;
                    *(float2*)(outk + base) = make_float2(v0, v1);
                    split2(v0, h0, l0); split2(v1, h1, l1);
                    *(uint32_t*)(g_kh + base) = packbf(h0, h1);
                    *(uint32_t*)(g_kl + base) = packbf(l0, l1);
                } else {
                    size_t base = (((size_t)(b * 16 + h)) * 2048 + 1024 + t) * 128 + d;
                    *(float2*)(outv + base) = make_float2(v0, v1);
                }
            }
        }
}

// ---------------------------------------------------------------------------
// Flash attention: 64 q-rows per CTA, 128 threads (4 warps x m16 x n128),
// 128-wide j-tiles, 2 CTAs/SM. Long q-tiles launch first.
// ---------------------------------------------------------------------------
__device__ __forceinline__ void fl_issue(uint32_t sb, int bh, int idx, int stg, int tid)
{
    const int jt = idx >> 3, ch = idx & 3;
    const int isV = (idx >> 2) & 1;
    const __nv_bfloat16 *sh, *sl;
    size_t ld;
    if (!isV) {
        sh = g_kh + ((size_t)bh * TOTL + jt * 128) * DD + ch * 32;
        sl = g_kl + ((size_t)bh * TOTL + jt * 128) * DD + ch * 32;
        ld = DD;
    } else {
        sh = g_vth + (size_t)bh * DD * TOTL + jt * 128 + ch * 32;
        sl = g_vtl + (size_t)bh * DD * TOTL + jt * 128 + ch * 32;
        ld = TOTL;
    }
    uint32_t st = sb + stg * FL_STAGE;
#pragma unroll
    for (int j = 0; j < 4; j++) {
        int u = tid + 128 * j, row = u >> 2, un = u & 3;
        uint32_t so = swz(row * 64 + un * 16);
        cpasync16(st + so,        sh + (size_t)row * ld + un * 8);
        cpasync16(st + 8192 + so, sl + (size_t)row * ld + un * 8);
    }
}

__global__ void __launch_bounds__(128) flash_mma()
{
    extern __shared__ __align__(1024) char smem[];
    const uint32_t sb = smem_u32(smem);
    const int bh = blockIdx.z;
    const int m0 = (15 - blockIdx.y) * 64;           // long CTAs first
    const int b = bh >> 4, h = bh & 15;
    const int tid = threadIdx.x;
    const int lane = tid & 31;
    const int w = tid >> 5;
    const int r0 = lane >> 2;
    const int NJ = (1215 + m0) >> 7;                 // ceil((1088+m0)/128)
    const int NCH = NJ * 8;
    const int off = 1024 + m0 - (NJ - 1) * 128;      // diag offset in last tile

    // Q tile: 64 rows, 4 k-chunks x (hi,lo), 4KB per chunk per part
#pragma unroll
    for (int c = 0; c < 4; c++)
#pragma unroll
        for (int j = 0; j < 2; j++) {
            int u = tid + 128 * j, row = u >> 2, un = u & 3;
            uint32_t so = c * 4096 + swz(row * 64 + un * 16);
            cpasync16(sb + FL_QOFF + so,
                      g_qh + ((size_t)bh * TT + m0 + row) * DD + c * 32 + un * 8);
            cpasync16(sb + FL_QOFF + 16384 + so,
                      g_ql + ((size_t)bh * TT + m0 + row) * DD + c * 32 + un * 8);
        }
    CP_COMMIT();
    fl_issue(sb, bh, 0, 0, tid); CP_COMMIT();
    fl_issue(sb, bh, 1, 1, tid); CP_COMMIT();
    fl_issue(sb, bh, 2, 2, tid); CP_COMMIT();

    uint32_t aoff[2], boff[8][2];
#pragma unroll
    for (int kk = 0; kk < 2; kk++) {
        int row = w * 16 + (lane & 15);
        aoff[kk] = swz(row * 64 + kk * 32 + ((lane >> 4) & 1) * 16);
    }
#pragma unroll
    for (int bt = 0; bt < 8; bt++)
#pragma unroll
        for (int kk = 0; kk < 2; kk++) {
            int row = bt * 16 + (lane & 7) + ((lane >> 4) & 1) * 8;
            boff[bt][kk] = swz(row * 64 + kk * 32 + ((lane >> 3) & 1) * 16);
        }

    float O[16][4];
#pragma unroll
    for (int i = 0; i < 16; i++)
#pragma unroll
        for (int k = 0; k < 4; k++) O[i][k] = 0.f;
    float ml0 = -1e30f, ml1 = -1e30f;
    float ll0 = 0.f, ll1 = 0.f;
    uint32_t ph[8][4], pl[8][4];

    int pf = 3, stage = 0;
    const float scale = 0.08838834764831845f;

    for (int jt = 0; jt < NJ; jt++) {
        float Sf[16][4];
        // ---- S phase: 4 K-chunks ----
#pragma unroll
        for (int ch = 0; ch < 4; ch++) {
            CP_WAIT2();
            __syncthreads();
            int pst = stage + 3; if (pst >= FL_NST) pst -= FL_NST;
            if (pf < NCH) fl_issue(sb, bh, pf, pst, tid);
            CP_COMMIT();
            pf++;
            const uint32_t stb = sb + stage * FL_STAGE;
            const uint32_t qb  = sb + FL_QOFF + ch * 4096;
            if (ch == 0) {
#pragma unroll
                for (int i = 0; i < 16; i++)
#pragma unroll
                    for (int k = 0; k < 4; k++) Sf[i][k] = 0.f;
            }
#pragma unroll
            for (int kk = 0; kk < 2; kk++) {
                uint32_t ahf[4], alf[4], bf[8][4];
                LDM4(ahf, qb + aoff[kk]);
                LDM4(alf, qb + 16384 + aoff[kk]);
#pragma unroll
                for (int bt = 0; bt < 8; bt++) LDM4(bf[bt], stb + boff[bt][kk]);
#pragma unroll
                for (int bt = 0; bt < 8; bt++) {
                    MMA16816(Sf[bt * 2 + 0], ahf, bf[bt][0], bf[bt][1]);
                    MMA16816(Sf[bt * 2 + 1], ahf, bf[bt][2], bf[bt][3]);
                }
#pragma unroll
                for (int bt = 0; bt < 8; bt++) {
                    MMA16816(Sf[bt * 2 + 0], alf, bf[bt][0], bf[bt][1]);
                    MMA16816(Sf[bt * 2 + 1], alf, bf[bt][2], bf[bt][3]);
                }
#pragma unroll
                for (int bt = 0; bt < 8; bt++) LDM4(bf[bt], stb + 8192 + boff[bt][kk]);
#pragma unroll
                for (int bt = 0; bt < 8; bt++) {
                    MMA16816(Sf[bt * 2 + 0], ahf, bf[bt][0], bf[bt][1]);
                    MMA16816(Sf[bt * 2 + 1], ahf, bf[bt][2], bf[bt][3]);
                }
            }
            if (++stage == FL_NST) stage = 0;
        }

        // ---- online softmax ----
#pragma unroll
        for (int nt = 0; nt < 16; nt++)
#pragma unroll
            for (int ci = 0; ci < 4; ci++) Sf[nt][ci] *= scale;
        if (jt == NJ - 1) {
#pragma unroll
            for (int nt = 0; nt < 16; nt++)
#pragma unroll
                for (int ci = 0; ci < 4; ci++) {
                    int jj = nt * 8 + (lane & 3) * 2 + (ci & 1);
                    int tl = w * 16 + r0 + ((ci >> 1) << 3);
                    if (jj > off + tl) Sf[nt][ci] = -1e30f;
                }
        }
        float mc0 = -1e30f, mc1 = -1e30f;
#pragma unroll
        for (int nt = 0; nt < 16; nt++) {
            mc0 = fmaxf(mc0, fmaxf(Sf[nt][0], Sf[nt][1]));
            mc1 = fmaxf(mc1, fmaxf(Sf[nt][2], Sf[nt][3]));
        }
        mc0 = fmaxf(mc0, __shfl_xor_sync(0xffffffffu, mc0, 1));
        mc0 = fmaxf(mc0, __shfl_xor_sync(0xffffffffu, mc0, 2));
        mc1 = fmaxf(mc1, __shfl_xor_sync(0xffffffffu, mc1, 1));
        mc1 = fmaxf(mc1, __shfl_xor_sync(0xffffffffu, mc1, 2));
        float mn0 = fmaxf(ml0, mc0), mn1 = fmaxf(ml1, mc1);
        float a0 = __expf(ml0 - mn0), a1 = __expf(ml1 - mn1);
        ml0 = mn0; ml1 = mn1;
        ll0 *= a0; ll1 *= a1;
#pragma unroll
        for (int nt = 0; nt < 16; nt++) {
            O[nt][0] *= a0; O[nt][1] *= a0;
            O[nt][2] *= a1; O[nt][3] *= a1;
        }
#pragma unroll
        for (int nt = 0; nt < 16; nt++) {
            float p0 = __expf(Sf[nt][0] - mn0), p1 = __expf(Sf[nt][1] - mn0);
            float p2 = __expf(Sf[nt][2] - mn1), p3 = __expf(Sf[nt][3] - mn1);
            ll0 += p0 + p1; ll1 += p2 + p3;
            __nv_bfloat16 h0, h1, h2, h3, l0, l1, l2, l3;
            split2(p0, h0, l0); split2(p1, h1, l1);
            split2(p2, h2, l2); split2(p3, h3, l3);
            int kkj = nt >> 1, half = nt & 1;
            ph[kkj][half * 2 + 0] = packbf(h0, h1);
            ph[kkj][half * 2 + 1] = packbf(h2, h3);
            pl[kkj][half * 2 + 0] = packbf(l0, l1);
            pl[kkj][half * 2 + 1] = packbf(l2, l3);
        }

        // ---- PV phase: 4 V^T-chunks ----
#pragma unroll
        for (int ch = 0; ch < 4; ch++) {
            CP_WAIT2();
            __syncthreads();
            int pst = stage + 3; if (pst >= FL_NST) pst -= FL_NST;
            if (pf < NCH) fl_issue(sb, bh, pf, pst, tid);
            CP_COMMIT();
            pf++;
            const uint32_t stb = sb + stage * FL_STAGE;
#pragma unroll
            for (int kk = 0; kk < 2; kk++) {
                const int kkj = ch * 2 + kk;
                uint32_t vf[8][4];
#pragma unroll
                for (int dt = 0; dt < 8; dt++) LDM4(vf[dt], stb + boff[dt][kk]);
#pragma unroll
                for (int dt = 0; dt < 8; dt++) {
                    MMA16816(O[dt * 2 + 0], ph[kkj], vf[dt][0], vf[dt][1]);
                    MMA16816(O[dt * 2 + 1], ph[kkj], vf[dt][2], vf[dt][3]);
                }
#pragma unroll
                for (int dt = 0; dt < 8; dt++) {
                    MMA16816(O[dt * 2 + 0], pl[kkj], vf[dt][0], vf[dt][1]);
                    MMA16816(O[dt * 2 + 1], pl[kkj], vf[dt][2], vf[dt][3]);
                }
#pragma unroll
                for (int dt = 0; dt < 8; dt++) LDM4(vf[dt], stb + 8192 + boff[dt][kk]);
#pragma unroll
                for (int dt = 0; dt < 8; dt++) {
                    MMA16816(O[dt * 2 + 0], ph[kkj], vf[dt][0], vf[dt][1]);
                    MMA16816(O[dt * 2 + 1], ph[kkj], vf[dt][2], vf[dt][3]);
                }
            }
            if (++stage == FL_NST) stage = 0;
        }
    }

    // ---- epilogue ----
    ll0 += __shfl_xor_sync(0xffffffffu, ll0, 1);
    ll0 += __shfl_xor_sync(0xffffffffu, ll0, 2);
    ll1 += __shfl_xor_sync(0xffffffffu, ll1, 1);
    ll1 += __shfl_xor_sync(0xffffffffu, ll1, 2);
    const float inv0 = 1.f / ll0, inv1 = 1.f / ll1;
    const int t0 = m0 + w * 16 + r0, t1 = t0 + 8;
#pragma unroll
    for (int nt = 0; nt < 16; nt++) {
        int d = nt * 8 + (lane & 3) * 2;
        float v0 = O[nt][0] * inv0, v1 = O[nt][1] * inv0;
        float v2 = O[nt][2] * inv1, v3 = O[nt][3] * inv1;
        size_t b0 = ((size_t)(b * 1024 + t0)) * 2048 + h * 128 + d;
        size_t b1 = ((size_t)(b * 1024 + t1)) * 2048 + h * 128 + d;
        __nv_bfloat16 h0, h1, h2, h3, l0, l1, l2, l3;
        split2(v0, h0, l0); split2(v1, h1, l1);
        split2(v2, h2, l2); split2(v3, h3, l3);
        *(uint32_t*)(g_aoh + b0) = packbf(h0, h1);
        *(uint32_t*)(g_aol + b0) = packbf(l0, l1);
        *(uint32_t*)(g_aoh + b1) = packbf(h2, h3);
        *(uint32_t*)(g_aol + b1) = packbf(l2, l3);
    }
}

// ---------------------------------------------------------------------------
// Output projection: out = ao @ Wp^T + bp
// ---------------------------------------------------------------------------
__global__ void __launch_bounds__(256, 2) proj_mma(const float* __restrict__ bp,
                                                    float* __restrict__ out)
{
    extern __shared__ __align__(1024) char smem[];
    const int m0 = blockIdx.y * 128, n0 = blockIdx.x * 128;
    Frag F;
    mma_mainloop(smem,
        g_aoh + (size_t)m0 * CC, g_aol + (size_t)m0 * CC,
        g_wph + (size_t)n0 * CC, g_wpl + (size_t)n0 * CC, CC, CC, 64, F);

    const int lane = threadIdx.x & 31, wid = threadIdx.x >> 5;
    const int wm = wid & 3, wn = wid >> 2;
#pragma unroll
    for (int mt = 0; mt < 2; mt++)
#pragma unroll
        for (int half = 0; half < 2; half++) {
            int m = m0 + wm * 32 + mt * 16 + lane / 4 + half * 8;
#pragma unroll
            for (int nt = 0; nt < 8; nt++) {
                int n = n0 + wn * 64 + nt * 8 + (lane & 3) * 2;
                float2 bias = *(const float2*)(bp + n);
                *(float2*)(out + (size_t)m * 2048 + n) =
                    make_float2(F.c[mt][nt][half * 2] + bias.x,
                                F.c[mt][nt][half * 2 + 1] + bias.y);
            }
        }
}

// ---------------------------------------------------------------------------
extern "C" void kernel_launch(void* const* d_in, const int* in_sizes, int n_in,
                              void* d_out, int out_size)
{
    (void)in_sizes; (void)n_in; (void)out_size;
    const float* x      = (const float*)d_in[0];
    const float* past_k = (const float*)d_in[1];
    const float* past_v = (const float*)d_in[2];
    const float* Wk     = (const float*)d_in[3];
    const float* Wq     = (const float*)d_in[4];
    const float* Wv     = (const float*)d_in[5];
    const float* Wp     = (const float*)d_in[6];
    const float* bp     = (const float*)d_in[7];

    float* out  = (float*)d_out;
    float* outk = out + (size_t)BB * TT * CC;
    float* outv = outk + (size_t)BHN * TOTL * DD;

    cudaFuncSetAttribute(qkv_mma,   cudaFuncAttributeMaxDynamicSharedMemorySize, DSMEM);
    cudaFuncSetAttribute(proj_mma,  cudaFuncAttributeMaxDynamicSharedMemorySize, DSMEM);
    cudaFuncSetAttribute(flash_mma, cudaFuncAttributeMaxDynamicSharedMemorySize, FL_DSMEM);

    // 1-2. fused prep
    prep_kernel<<<dim3(4096, 7), 256>>>(
        (const float4*)x,  (const float4*)Wq, (const float4*)Wk,
        (const float4*)Wv, (const float4*)Wp, (const float4*)past_k,
        (const float4*)past_v, (float4*)outk, (float4*)outv);

    // 3. QKV projection
    qkv_mma<<<dim3(16, 16, 3), 256, DSMEM>>>(outk, outv);

    // 4. transpose+split V cache
    vtrans_kernel<<<dim3(64, 4, 32), 256>>>(outv);

    // 5-7. fused flash attention (64 q-rows per CTA, 2 CTAs/SM, long first)
    flash_mma<<<dim3(1, 16, 32), 128, FL_DSMEM>>>();

    // 8. output projection + bias
    proj_mma<<<dim3(16, 16), 256, DSMEM>>>(bp, out);
}